// round 6
// baseline (speedup 1.0000x reference)
#include <cuda_runtime.h>
#include <cuda_bf16.h>
#include <cstdint>

// DeployPostProcessor: per-batch top-300 of sigmoid(logits[B=256,Q=1000,C=80]).
// K1: ballot-free streaming prefilter (x >= 2.2999) -> global scratch (~858/batch)
// K2: rank-select to ~305 via 1024-bucket hist, bitonic-512 sort, emit.

#define BATCH       256
#define NPER        80000
#define N4          20000
#define NCLS        80
#define TOPK        300
#define CAP         1536
#define PTHRESH     2.2999f    // count(x>=2.3) ~ 858 +- 29 per 80k N(0,1)

#define K1_THREADS  256
#define K1_F4       2500       // float4 per chunk (8 chunks/batch)
#define K1_ITERS    10

#define K2_THREADS  512

__device__ unsigned long long g_keys[BATCH * CAP];
__device__ unsigned int       g_cnt[BATCH];

// monotone key: ascending float -> ascending uint32
__device__ __forceinline__ uint32_t fkey(float x) {
    uint32_t b = __float_as_uint(x);
    return b ^ ((uint32_t)((int32_t)b >> 31) | 0x80000000u);
}

__device__ __forceinline__ unsigned long long make_key(float x, uint32_t idx) {
    float s = 1.0f / (1.0f + expf(-x));
    return ((unsigned long long)__float_as_uint(s) << 32)
         | (unsigned long long)(0xFFFFFFFFu - idx);
}

// ================= Kernel 1: streaming prefilter (no ballots) =================
__global__ __launch_bounds__(K1_THREADS)
void prefilter_kernel(const float* __restrict__ logits)
{
    const int blk   = blockIdx.x;
    const int b     = blk >> 3;
    const int chunk = blk & 7;
    const float4* lg4 = (const float4*)(logits + (size_t)b * NPER) + chunk * K1_F4;
    unsigned long long* kb = g_keys + (size_t)b * CAP;
    const uint32_t idxbase = (uint32_t)(chunk * K1_F4) * 4u;

    float4 v[K1_ITERS];
    #pragma unroll
    for (int it = 0; it < K1_ITERS; ++it) {
        int i = threadIdx.x + it * K1_THREADS;
        if (i < K1_F4) v[it] = lg4[i];
        else { v[it].x = v[it].y = v[it].z = v[it].w = -1e30f; }
    }

    #pragma unroll
    for (int it = 0; it < K1_ITERS; ++it) {
        uint32_t i4 = idxbase + (uint32_t)(threadIdx.x + it * K1_THREADS) * 4u;
        float4 w = v[it];
        if (w.x >= PTHRESH) { uint32_t p = atomicAdd(&g_cnt[b], 1u); if (p < CAP) kb[p] = make_key(w.x, i4 + 0); }
        if (w.y >= PTHRESH) { uint32_t p = atomicAdd(&g_cnt[b], 1u); if (p < CAP) kb[p] = make_key(w.y, i4 + 1); }
        if (w.z >= PTHRESH) { uint32_t p = atomicAdd(&g_cnt[b], 1u); if (p < CAP) kb[p] = make_key(w.z, i4 + 2); }
        if (w.w >= PTHRESH) { uint32_t p = atomicAdd(&g_cnt[b], 1u); if (p < CAP) kb[p] = make_key(w.w, i4 + 3); }
    }
}

// ================= Kernel 2: rank-select + sort-512 + emit =================
__global__ __launch_bounds__(K2_THREADS, 2)
void sort_emit_kernel(const float* __restrict__ logits,
                      const float* __restrict__ boxes,
                      float* __restrict__ out)
{
    extern __shared__ unsigned char raw[];
    unsigned long long* keys  = (unsigned long long*)raw;            // 2048 u64 (16KB)
    uint32_t*           fbh   = (uint32_t*)raw;                      // 4096 u32 alias (fallback hist)
    unsigned long long* keys2 = (unsigned long long*)(raw + 16384);  // 512 u64 (4KB)
    uint32_t*           hist  = (uint32_t*)(raw + 16384 + 4096);     // 1024 u32 (4KB)
    uint32_t*           S     = (uint32_t*)(raw + 16384 + 8192);     // 512 u32 (2KB)
    uint32_t*           scal  = (uint32_t*)(raw + 16384 + 8192 + 2048);

    const int tid = threadIdx.x;
    const int b   = blockIdx.x;

    // RACE FIX: single thread reads+resets the global counter; broadcast via smem
    if (tid == 0) {
        scal[3] = g_cnt[b];
        g_cnt[b] = 0;
        scal[1] = 0;
        scal[2] = 0;
    }
    __syncthreads();
    uint32_t cnt = scal[3];          // uniform across the CTA

    unsigned long long* A = keys;
    int m = 0;
    int mode = 1;   // 0 = hybrid-512, 1 = generic

    if (cnt >= TOPK && cnt <= CAP) {
        // ---- fast path ----
        const unsigned long long* kb = g_keys + (size_t)b * CAP;
        for (int i = tid; i < (int)cnt; i += K2_THREADS) keys[i] = kb[i];
        for (int i = tid; i < 1024; i += K2_THREADS) hist[i] = 0;
        __syncthreads();

        // histogram on sigmoid mantissa bits [22:13] (binade [0.5,1) assumed; guarded)
        for (int i = tid; i < (int)cnt; i += K2_THREADS) {
            uint32_t sb = (uint32_t)(keys[i] >> 32);
            if ((sb >> 23) != 0x7Eu) scal[2] = 1;
            atomicAdd(&hist[(sb >> 13) & 1023u], 1u);
        }
        __syncthreads();

        if (scal[2] == 0) {
            uint32_t s = hist[2 * tid] + hist[2 * tid + 1];
            S[tid] = s; __syncthreads();
            for (int off = 1; off < K2_THREADS; off <<= 1) {
                uint32_t v2 = S[tid] + ((tid + off < K2_THREADS) ? S[tid + off] : 0u);
                __syncthreads(); S[tid] = v2; __syncthreads();
            }
            {
                uint32_t after = (tid == K2_THREADS - 1) ? 0u : S[tid + 1];
                uint32_t mine  = S[tid];
                if (after < TOPK && mine >= TOPK) {
                    uint32_t run = after + hist[2 * tid + 1];
                    scal[0] = (run >= TOPK) ? (uint32_t)(2 * tid + 1) : (uint32_t)(2 * tid);
                }
            }
            __syncthreads();
            uint32_t tb = scal[0];

            // compact keys with bucket >= tb (superset of top-300, keeps tie-buckets whole)
            for (int i = tid; i < (int)cnt; i += K2_THREADS) {
                unsigned long long k = keys[i];
                uint32_t bkt = (((uint32_t)(k >> 32)) >> 13) & 1023u;
                if (bkt >= tb) { uint32_t p = atomicAdd(&scal[1], 1u); if (p < K2_THREADS) keys2[p] = k; }
            }
            __syncthreads();
            uint32_t sc = scal[1];
            if (sc <= K2_THREADS) {
                A = keys2; m = K2_THREADS; mode = 0;
                if ((uint32_t)tid >= sc) keys2[tid] = 0ull;
            } else {
                m = 512; while (m < (int)cnt) m <<= 1;
                for (int i = tid; i < m; i += K2_THREADS) if ((uint32_t)i >= cnt) keys[i] = 0ull;
            }
        } else {
            m = 512; while (m < (int)cnt) m <<= 1;
            for (int i = tid; i < m; i += K2_THREADS) if ((uint32_t)i >= cnt) keys[i] = 0ull;
        }
    } else {
        // ---- full fallback: exact 4096-bucket histogram select (never on N(0,1)) ----
        const float4* lg4 = (const float4*)(logits + (size_t)b * NPER);
        for (int i = tid; i < 4096; i += K2_THREADS) fbh[i] = 0;
        __syncthreads();
        for (int i = tid; i < N4; i += K2_THREADS) {
            float4 v = lg4[i];
            atomicAdd(&fbh[fkey(v.x) >> 20], 1u);
            atomicAdd(&fbh[fkey(v.y) >> 20], 1u);
            atomicAdd(&fbh[fkey(v.z) >> 20], 1u);
            atomicAdd(&fbh[fkey(v.w) >> 20], 1u);
        }
        __syncthreads();
        uint32_t csum = 0;
        #pragma unroll
        for (int c = 0; c < 8; ++c) csum += fbh[tid * 8 + c];
        S[tid] = csum; __syncthreads();
        for (int off = 1; off < K2_THREADS; off <<= 1) {
            uint32_t v2 = S[tid] + ((tid + off < K2_THREADS) ? S[tid + off] : 0u);
            __syncthreads(); S[tid] = v2; __syncthreads();
        }
        {
            uint32_t after = (tid == K2_THREADS - 1) ? 0u : S[tid + 1];
            uint32_t mine  = S[tid];
            if (after < TOPK && mine >= TOPK) {
                uint32_t run = after;
                for (int bk = tid * 8 + 7; bk >= tid * 8; --bk) {
                    run += fbh[bk];
                    if (run >= TOPK) { scal[0] = (uint32_t)bk; break; }
                }
            }
        }
        __syncthreads();
        uint32_t tb = scal[0];
        if (tb > 0) tb -= 1;                 // one-bucket margin for sigmoid ties
        const uint32_t thr = tb << 20;
        __syncthreads();                      // done with fbh; keys region reusable
        for (int i = tid; i < N4; i += K2_THREADS) {
            float4 v = lg4[i];
            float vv[4] = {v.x, v.y, v.z, v.w};
            #pragma unroll
            for (int c = 0; c < 4; ++c) {
                if (fkey(vv[c]) >= thr) {
                    uint32_t p = atomicAdd(&scal[1], 1u);
                    if (p < 2048u) keys[p] = make_key(vv[c], (uint32_t)(i * 4 + c));
                }
            }
        }
        __syncthreads();
        uint32_t c2 = scal[1]; if (c2 > 2048u) c2 = 2048u;
        m = 512; while (m < (int)c2) m <<= 1;
        for (int i = tid; i < m; i += K2_THREADS) if ((uint32_t)i >= c2) keys[i] = 0ull;
    }
    __syncthreads();

    // ================= sort (descending) =================
    if (mode == 0) {
        // hybrid bitonic-512, 1 element/thread
        unsigned long long v = A[tid];
        #pragma unroll
        for (int k = 2; k <= 32; k <<= 1) {
            #pragma unroll
            for (int j = k >> 1; j; j >>= 1) {
                unsigned long long o = __shfl_xor_sync(0xffffffffu, v, j);
                bool mx = ((tid & k) == 0) ^ ((tid & j) != 0);
                v = mx ? (v > o ? v : o) : (v < o ? v : o);
            }
        }
        A[tid] = v; __syncthreads();
        #pragma unroll
        for (int k = 64; k <= 512; k <<= 1) {
            #pragma unroll
            for (int j = k >> 1; j >= 32; j >>= 1) {
                int ixj = tid ^ j;
                if (ixj > tid) {
                    unsigned long long a = A[tid], c = A[ixj];
                    bool desc = ((tid & k) == 0);
                    if (desc ? (a < c) : (a > c)) { A[tid] = c; A[ixj] = a; }
                }
                __syncthreads();
            }
            v = A[tid];
            bool desck = ((tid & k) == 0);
            #pragma unroll
            for (int j = 16; j; j >>= 1) {
                unsigned long long o = __shfl_xor_sync(0xffffffffu, v, j);
                bool mx = desck ^ ((tid & j) != 0);
                v = mx ? (v > o ? v : o) : (v < o ? v : o);
            }
            A[tid] = v; __syncthreads();
        }
    } else {
        // generic bitonic over m (512..2048), slot-strided
        for (int k = 2; k <= m; k <<= 1) {
            for (int j = k >> 1; j > 0; j >>= 1) {
                for (int i = tid; i < m; i += K2_THREADS) {
                    int ixj = i ^ j;
                    if (ixj > i) {
                        unsigned long long a = A[i], c = A[ixj];
                        bool desc = ((i & k) == 0);
                        if (desc ? (a < c) : (a > c)) { A[i] = c; A[ixj] = a; }
                    }
                }
                __syncthreads();
            }
        }
    }

    // ================= emit top 300 =================
    if (tid < TOPK) {
        unsigned long long key = A[tid];
        uint32_t sbits = (uint32_t)(key >> 32);
        uint32_t idx   = 0xFFFFFFFFu - (uint32_t)(key & 0xFFFFFFFFull);
        if (idx >= NPER) idx = 0;          // OOB guard: never triggers on valid paths
        float score = __uint_as_float(sbits);
        int   label = (int)(idx % NCLS);
        int   q     = (int)(idx / NCLS);

        const float4 bx = ((const float4*)boxes)[b * 1000 + q];
        float cx = bx.x, cy = bx.y, w = bx.z, h = bx.w;

        int base = b * TOPK + tid;
        out[base] = (float)label;
        float* bo = out + BATCH * TOPK + (size_t)base * 4;
        bo[0] = cx - 0.5f * w;
        bo[1] = cy - 0.5f * h;
        bo[2] = cx + 0.5f * w;
        bo[3] = cy + 0.5f * h;
        out[BATCH * TOPK * 5 + base] = score;
    }
}

extern "C" void kernel_launch(void* const* d_in, const int* in_sizes, int n_in,
                              void* d_out, int out_size)
{
    const float* logits = (const float*)d_in[0];
    const float* boxes  = (const float*)d_in[1];
    float* out = (float*)d_out;

    const int smem2 = 16384 + 4096 + 4096 + 2048 + 64;   // 26,688 B < 48KB default
    prefilter_kernel<<<BATCH * 8, K1_THREADS>>>(logits);
    sort_emit_kernel<<<BATCH, K2_THREADS, smem2>>>(logits, boxes, out);
}

// round 10
// speedup vs baseline: 1.0222x; 1.0222x over previous
#include <cuda_runtime.h>
#include <cuda_bf16.h>
#include <cstdint>

// DeployPostProcessor: per-batch top-300 of sigmoid(logits[B=256,Q=1000,C=80]).
// Fused single kernel: 2 CTAs per batch stream half each (MLP=4 front-batch),
// candidates -> global scratch; last-arriving CTA rank-selects + sorts + emits.

#define BATCH       256
#define NPER        80000
#define N4          20000
#define HALF4       10000      // float4 per half-batch
#define NCLS        80
#define TOPK        300
#define CAP         1536
#define PTHRESH     2.2999f    // count(x>=2.3) ~ 858 +- 29 per 80k N(0,1)

#define NT          512        // threads per CTA

__device__ unsigned long long g_keys[BATCH * CAP];
__device__ unsigned int       g_cnt[BATCH];
__device__ unsigned int       g_done[BATCH];

// monotone key: ascending float -> ascending uint32
__device__ __forceinline__ uint32_t fkey(float x) {
    uint32_t b = __float_as_uint(x);
    return b ^ ((uint32_t)((int32_t)b >> 31) | 0x80000000u);
}

__device__ __forceinline__ unsigned long long make_key(float x, uint32_t idx) {
    float s = 1.0f / (1.0f + expf(-x));
    return ((unsigned long long)__float_as_uint(s) << 32)
         | (unsigned long long)(0xFFFFFFFFu - idx);
}

__global__ __launch_bounds__(NT)
void postproc_fused(const float* __restrict__ logits,
                    const float* __restrict__ boxes,
                    float* __restrict__ out)
{
    extern __shared__ unsigned char raw[];
    unsigned long long* keys  = (unsigned long long*)raw;            // 2048 u64 (16KB)
    uint32_t*           fbh   = (uint32_t*)raw;                      // 4096 u32 alias (fallback)
    unsigned long long* keys2 = (unsigned long long*)(raw + 16384);  // 512 u64 (4KB)
    uint32_t*           hist  = (uint32_t*)(raw + 16384 + 4096);     // 1024 u32 (4KB)
    uint32_t*           S     = (uint32_t*)(raw + 16384 + 8192);     // 512 u32 (2KB)
    uint32_t*           scal  = (uint32_t*)(raw + 16384 + 8192 + 2048);

    const int tid  = threadIdx.x;
    const int b    = blockIdx.x >> 1;
    const int half = blockIdx.x & 1;

    // ================= phase 1: stream half-batch, MLP=4 =================
    {
        const float4* lg4 = (const float4*)(logits + (size_t)b * NPER) + half * HALF4;
        unsigned long long* kb = g_keys + (size_t)b * CAP;
        const uint32_t idxbase = (uint32_t)(half * HALF4) * 4u;

        for (int base = 0; base < HALF4; base += 4 * NT) {
            int i0 = base + tid;
            int i1 = i0 + NT, i2 = i1 + NT, i3 = i2 + NT;
            float4 v0, v1, v2, v3;
            const float4 sent = make_float4(-1e30f, -1e30f, -1e30f, -1e30f);
            v0 = (i0 < HALF4) ? lg4[i0] : sent;
            v1 = (i1 < HALF4) ? lg4[i1] : sent;
            v2 = (i2 < HALF4) ? lg4[i2] : sent;
            v3 = (i3 < HALF4) ? lg4[i3] : sent;

            #define PROC(vv, ii)                                                        \
                if ((vv).x >= PTHRESH) { uint32_t p = atomicAdd(&g_cnt[b], 1u);         \
                    if (p < CAP) kb[p] = make_key((vv).x, idxbase + (uint32_t)(ii)*4u + 0); } \
                if ((vv).y >= PTHRESH) { uint32_t p = atomicAdd(&g_cnt[b], 1u);         \
                    if (p < CAP) kb[p] = make_key((vv).y, idxbase + (uint32_t)(ii)*4u + 1); } \
                if ((vv).z >= PTHRESH) { uint32_t p = atomicAdd(&g_cnt[b], 1u);         \
                    if (p < CAP) kb[p] = make_key((vv).z, idxbase + (uint32_t)(ii)*4u + 2); } \
                if ((vv).w >= PTHRESH) { uint32_t p = atomicAdd(&g_cnt[b], 1u);         \
                    if (p < CAP) kb[p] = make_key((vv).w, idxbase + (uint32_t)(ii)*4u + 3); }
            PROC(v0, i0) PROC(v1, i1) PROC(v2, i2) PROC(v3, i3)
            #undef PROC
        }
    }

    // ================= phase 2: last CTA of the pair proceeds =================
    __threadfence();
    __syncthreads();
    if (tid == 0) scal[4] = atomicAdd(&g_done[b], 1u);
    __syncthreads();
    if (scal[4] != 1u) return;           // first finisher exits; second sorts

    if (tid == 0) {
        scal[3] = g_cnt[b];
        g_cnt[b]  = 0;                   // reset for next graph replay
        g_done[b] = 0;
        scal[1] = 0;
        scal[2] = 0;
    }
    __syncthreads();
    uint32_t cnt = scal[3];

    unsigned long long* A = keys;
    int m = 0;
    int mode = 1;   // 0 = hybrid-512, 1 = generic

    if (cnt >= TOPK && cnt <= CAP) {
        // ---- fast path: rank-select on sigmoid mantissa ----
        const unsigned long long* kb = g_keys + (size_t)b * CAP;
        for (int i = tid; i < (int)cnt; i += NT) keys[i] = kb[i];
        for (int i = tid; i < 1024; i += NT) hist[i] = 0;
        __syncthreads();

        for (int i = tid; i < (int)cnt; i += NT) {
            uint32_t sb = (uint32_t)(keys[i] >> 32);
            if ((sb >> 23) != 0x7Eu) scal[2] = 1;   // binade guard
            atomicAdd(&hist[(sb >> 13) & 1023u], 1u);
        }
        __syncthreads();

        if (scal[2] == 0) {
            uint32_t s = hist[2 * tid] + hist[2 * tid + 1];
            S[tid] = s; __syncthreads();
            for (int off = 1; off < NT; off <<= 1) {
                uint32_t v2 = S[tid] + ((tid + off < NT) ? S[tid + off] : 0u);
                __syncthreads(); S[tid] = v2; __syncthreads();
            }
            {
                uint32_t after = (tid == NT - 1) ? 0u : S[tid + 1];
                uint32_t mine  = S[tid];
                if (after < TOPK && mine >= TOPK) {
                    uint32_t run = after + hist[2 * tid + 1];
                    scal[0] = (run >= TOPK) ? (uint32_t)(2 * tid + 1) : (uint32_t)(2 * tid);
                }
            }
            __syncthreads();
            uint32_t tb = scal[0];

            for (int i = tid; i < (int)cnt; i += NT) {
                unsigned long long k = keys[i];
                uint32_t bkt = (((uint32_t)(k >> 32)) >> 13) & 1023u;
                if (bkt >= tb) { uint32_t p = atomicAdd(&scal[1], 1u); if (p < NT) keys2[p] = k; }
            }
            __syncthreads();
            uint32_t sc = scal[1];
            if (sc <= NT) {
                A = keys2; m = NT; mode = 0;
                if ((uint32_t)tid >= sc) keys2[tid] = 0ull;
            } else {
                m = 512; while (m < (int)cnt) m <<= 1;
                for (int i = tid; i < m; i += NT) if ((uint32_t)i >= cnt) keys[i] = 0ull;
            }
        } else {
            m = 512; while (m < (int)cnt) m <<= 1;
            for (int i = tid; i < m; i += NT) if ((uint32_t)i >= cnt) keys[i] = 0ull;
        }
    } else {
        // ---- full fallback: exact 4096-bucket histogram select ----
        const float4* lg4 = (const float4*)(logits + (size_t)b * NPER);
        for (int i = tid; i < 4096; i += NT) fbh[i] = 0;
        __syncthreads();
        for (int i = tid; i < N4; i += NT) {
            float4 v = lg4[i];
            atomicAdd(&fbh[fkey(v.x) >> 20], 1u);
            atomicAdd(&fbh[fkey(v.y) >> 20], 1u);
            atomicAdd(&fbh[fkey(v.z) >> 20], 1u);
            atomicAdd(&fbh[fkey(v.w) >> 20], 1u);
        }
        __syncthreads();
        uint32_t csum = 0;
        #pragma unroll
        for (int c = 0; c < 8; ++c) csum += fbh[tid * 8 + c];
        S[tid] = csum; __syncthreads();
        for (int off = 1; off < NT; off <<= 1) {
            uint32_t v2 = S[tid] + ((tid + off < NT) ? S[tid + off] : 0u);
            __syncthreads(); S[tid] = v2; __syncthreads();
        }
        {
            uint32_t after = (tid == NT - 1) ? 0u : S[tid + 1];
            uint32_t mine  = S[tid];
            if (after < TOPK && mine >= TOPK) {
                uint32_t run = after;
                for (int bk = tid * 8 + 7; bk >= tid * 8; --bk) {
                    run += fbh[bk];
                    if (run >= TOPK) { scal[0] = (uint32_t)bk; break; }
                }
            }
        }
        __syncthreads();
        uint32_t tb = scal[0];
        if (tb > 0) tb -= 1;                 // one-bucket margin for sigmoid ties
        const uint32_t thr = tb << 20;
        __syncthreads();
        for (int i = tid; i < N4; i += NT) {
            float4 v = lg4[i];
            float vv[4] = {v.x, v.y, v.z, v.w};
            #pragma unroll
            for (int c = 0; c < 4; ++c) {
                if (fkey(vv[c]) >= thr) {
                    uint32_t p = atomicAdd(&scal[1], 1u);
                    if (p < 2048u) keys[p] = make_key(vv[c], (uint32_t)(i * 4 + c));
                }
            }
        }
        __syncthreads();
        uint32_t c2 = scal[1]; if (c2 > 2048u) c2 = 2048u;
        m = 512; while (m < (int)c2) m <<= 1;
        for (int i = tid; i < m; i += NT) if ((uint32_t)i >= c2) keys[i] = 0ull;
    }
    __syncthreads();

    // ================= sort (descending) =================
    if (mode == 0) {
        // hybrid bitonic-512, 1 element/thread
        unsigned long long v = A[tid];
        #pragma unroll
        for (int k = 2; k <= 32; k <<= 1) {
            #pragma unroll
            for (int j = k >> 1; j; j >>= 1) {
                unsigned long long o = __shfl_xor_sync(0xffffffffu, v, j);
                bool mx = ((tid & k) == 0) ^ ((tid & j) != 0);
                v = mx ? (v > o ? v : o) : (v < o ? v : o);
            }
        }
        A[tid] = v; __syncthreads();
        #pragma unroll
        for (int k = 64; k <= 512; k <<= 1) {
            #pragma unroll
            for (int j = k >> 1; j >= 32; j >>= 1) {
                int ixj = tid ^ j;
                if (ixj > tid) {
                    unsigned long long a = A[tid], c = A[ixj];
                    bool desc = ((tid & k) == 0);
                    if (desc ? (a < c) : (a > c)) { A[tid] = c; A[ixj] = a; }
                }
                __syncthreads();
            }
            v = A[tid];
            bool desck = ((tid & k) == 0);
            #pragma unroll
            for (int j = 16; j; j >>= 1) {
                unsigned long long o = __shfl_xor_sync(0xffffffffu, v, j);
                bool mx = desck ^ ((tid & j) != 0);
                v = mx ? (v > o ? v : o) : (v < o ? v : o);
            }
            A[tid] = v; __syncthreads();
        }
    } else {
        // generic bitonic over m (512..2048), slot-strided
        for (int k = 2; k <= m; k <<= 1) {
            for (int j = k >> 1; j > 0; j >>= 1) {
                for (int i = tid; i < m; i += NT) {
                    int ixj = i ^ j;
                    if (ixj > i) {
                        unsigned long long a = A[i], c = A[ixj];
                        bool desc = ((i & k) == 0);
                        if (desc ? (a < c) : (a > c)) { A[i] = c; A[ixj] = a; }
                    }
                }
                __syncthreads();
            }
        }
    }

    // ================= emit top 300 =================
    if (tid < TOPK) {
        unsigned long long key = A[tid];
        uint32_t sbits = (uint32_t)(key >> 32);
        uint32_t idx   = 0xFFFFFFFFu - (uint32_t)(key & 0xFFFFFFFFull);
        if (idx >= NPER) idx = 0;          // OOB guard: never triggers on valid paths
        float score = __uint_as_float(sbits);
        int   label = (int)(idx % NCLS);
        int   q     = (int)(idx / NCLS);

        const float4 bx = ((const float4*)boxes)[b * 1000 + q];
        float cx = bx.x, cy = bx.y, w = bx.z, h = bx.w;

        int base = b * TOPK + tid;
        out[base] = (float)label;
        float* bo = out + BATCH * TOPK + (size_t)base * 4;
        bo[0] = cx - 0.5f * w;
        bo[1] = cy - 0.5f * h;
        bo[2] = cx + 0.5f * w;
        bo[3] = cy + 0.5f * h;
        out[BATCH * TOPK * 5 + base] = score;
    }
}

extern "C" void kernel_launch(void* const* d_in, const int* in_sizes, int n_in,
                              void* d_out, int out_size)
{
    const float* logits = (const float*)d_in[0];
    const float* boxes  = (const float*)d_in[1];
    float* out = (float*)d_out;

    const int smem = 16384 + 4096 + 4096 + 2048 + 64;   // 26,688 B < 48KB default
    postproc_fused<<<BATCH * 2, NT, smem>>>(logits, boxes, out);
}

// round 11
// speedup vs baseline: 2.2600x; 2.2108x over previous
#include <cuda_runtime.h>
#include <cuda_bf16.h>
#include <cstdint>

// DeployPostProcessor: per-batch top-300 of sigmoid(logits[B=256,Q=1000,C=80]).
// Fused: 2 CTAs/batch stream half each with SMEM candidate collection (MLP=4),
// one bulk global handoff per CTA, last arriver rank-selects + sorts + emits.

#define BATCH       256
#define NPER        80000
#define N4          20000
#define HALF4       10000      // float4 per half-batch
#define NCLS        80
#define TOPK        300
#define CAP         1536       // global candidate capacity per batch
#define SCAP        2048       // smem candidate capacity per CTA
#define PTHRESH     2.2999f    // count(x>=2.3) ~ 858 +- 29 per 80k N(0,1)

#define NT          512        // threads per CTA

__device__ unsigned long long g_keys[BATCH * CAP];
__device__ unsigned int       g_pos[BATCH];
__device__ unsigned int       g_done[BATCH];

// monotone key: ascending float -> ascending uint32
__device__ __forceinline__ uint32_t fkey(float x) {
    uint32_t b = __float_as_uint(x);
    return b ^ ((uint32_t)((int32_t)b >> 31) | 0x80000000u);
}

__device__ __forceinline__ unsigned long long make_key(float x, uint32_t idx) {
    float s = 1.0f / (1.0f + expf(-x));
    return ((unsigned long long)__float_as_uint(s) << 32)
         | (unsigned long long)(0xFFFFFFFFu - idx);
}

__global__ __launch_bounds__(NT)
void postproc_fused(const float* __restrict__ logits,
                    const float* __restrict__ boxes,
                    float* __restrict__ out)
{
    extern __shared__ unsigned char raw[];
    unsigned long long* keys  = (unsigned long long*)raw;            // 2048 u64 (16KB), also scand
    uint32_t*           fbh   = (uint32_t*)raw;                      // 4096 u32 alias (fallback)
    unsigned long long* keys2 = (unsigned long long*)(raw + 16384);  // 512 u64 (4KB)
    uint32_t*           hist  = (uint32_t*)(raw + 16384 + 4096);     // 1024 u32 (4KB)
    uint32_t*           S     = (uint32_t*)(raw + 16384 + 8192);     // 512 u32 (2KB)
    uint32_t*           scal  = (uint32_t*)(raw + 16384 + 8192 + 2048);

    unsigned long long* scand = keys;   // smem candidate list (alias; reloaded later)

    const int tid  = threadIdx.x;
    const int b    = blockIdx.x >> 1;
    const int half = blockIdx.x & 1;

    if (tid == 0) scal[5] = 0;          // smem candidate counter
    __syncthreads();

    // ================= phase 1: stream half-batch, smem atomics, MLP=4 =================
    {
        const float4* lg4 = (const float4*)(logits + (size_t)b * NPER) + half * HALF4;
        const uint32_t idxbase = (uint32_t)(half * HALF4) * 4u;
        const float4 sent = make_float4(-1e30f, -1e30f, -1e30f, -1e30f);

        for (int base = 0; base < HALF4; base += 4 * NT) {
            int i0 = base + tid;
            int i1 = i0 + NT, i2 = i1 + NT, i3 = i2 + NT;
            float4 v0 = (i0 < HALF4) ? lg4[i0] : sent;
            float4 v1 = (i1 < HALF4) ? lg4[i1] : sent;
            float4 v2 = (i2 < HALF4) ? lg4[i2] : sent;
            float4 v3 = (i3 < HALF4) ? lg4[i3] : sent;

            #define PROC(vv, ii)                                                            \
                if ((vv).x >= PTHRESH) { uint32_t p = atomicAdd(&scal[5], 1u);              \
                    if (p < SCAP) scand[p] = make_key((vv).x, idxbase + (uint32_t)(ii)*4u + 0); } \
                if ((vv).y >= PTHRESH) { uint32_t p = atomicAdd(&scal[5], 1u);              \
                    if (p < SCAP) scand[p] = make_key((vv).y, idxbase + (uint32_t)(ii)*4u + 1); } \
                if ((vv).z >= PTHRESH) { uint32_t p = atomicAdd(&scal[5], 1u);              \
                    if (p < SCAP) scand[p] = make_key((vv).z, idxbase + (uint32_t)(ii)*4u + 2); } \
                if ((vv).w >= PTHRESH) { uint32_t p = atomicAdd(&scal[5], 1u);              \
                    if (p < SCAP) scand[p] = make_key((vv).w, idxbase + (uint32_t)(ii)*4u + 3); }
            PROC(v0, i0) PROC(v1, i1) PROC(v2, i2) PROC(v3, i3)
            #undef PROC
        }
    }
    __syncthreads();

    // ================= phase 2: bulk handoff to global =================
    uint32_t mycnt = scal[5]; if (mycnt > SCAP) mycnt = SCAP;
    if (tid == 0) scal[6] = atomicAdd(&g_pos[b], mycnt);
    __syncthreads();
    uint32_t gbase = scal[6];
    unsigned long long* kb = g_keys + (size_t)b * CAP;
    for (uint32_t i = tid; i < mycnt; i += NT) {
        uint32_t p = gbase + i;
        if (p < CAP) kb[p] = scand[i];
    }
    __threadfence();
    __syncthreads();
    if (tid == 0) scal[4] = atomicAdd(&g_done[b], 1u);
    __syncthreads();
    if (scal[4] != 1u) return;           // first finisher exits; second sorts
    __threadfence();

    if (tid == 0) {
        scal[3] = g_pos[b];
        g_pos[b]  = 0;                   // reset for next graph replay
        g_done[b] = 0;
        scal[1] = 0;
        scal[2] = 0;
    }
    __syncthreads();
    uint32_t cnt = scal[3];

    unsigned long long* A = keys;
    int m = 0;
    int mode = 1;   // 0 = hybrid-512, 1 = generic

    if (cnt >= TOPK && cnt <= CAP) {
        // ---- fast path: rank-select on sigmoid mantissa ----
        for (int i = tid; i < (int)cnt; i += NT) keys[i] = kb[i];
        for (int i = tid; i < 1024; i += NT) hist[i] = 0;
        __syncthreads();

        for (int i = tid; i < (int)cnt; i += NT) {
            uint32_t sb = (uint32_t)(keys[i] >> 32);
            if ((sb >> 23) != 0x7Eu) scal[2] = 1;   // binade guard
            atomicAdd(&hist[(sb >> 13) & 1023u], 1u);
        }
        __syncthreads();

        if (scal[2] == 0) {
            uint32_t s = hist[2 * tid] + hist[2 * tid + 1];
            S[tid] = s; __syncthreads();
            for (int off = 1; off < NT; off <<= 1) {
                uint32_t v2 = S[tid] + ((tid + off < NT) ? S[tid + off] : 0u);
                __syncthreads(); S[tid] = v2; __syncthreads();
            }
            {
                uint32_t after = (tid == NT - 1) ? 0u : S[tid + 1];
                uint32_t mine  = S[tid];
                if (after < TOPK && mine >= TOPK) {
                    uint32_t run = after + hist[2 * tid + 1];
                    scal[0] = (run >= TOPK) ? (uint32_t)(2 * tid + 1) : (uint32_t)(2 * tid);
                }
            }
            __syncthreads();
            uint32_t tb = scal[0];

            for (int i = tid; i < (int)cnt; i += NT) {
                unsigned long long k = keys[i];
                uint32_t bkt = (((uint32_t)(k >> 32)) >> 13) & 1023u;
                if (bkt >= tb) { uint32_t p = atomicAdd(&scal[1], 1u); if (p < NT) keys2[p] = k; }
            }
            __syncthreads();
            uint32_t sc = scal[1];
            if (sc <= NT) {
                A = keys2; m = NT; mode = 0;
                if ((uint32_t)tid >= sc) keys2[tid] = 0ull;
            } else {
                m = 512; while (m < (int)cnt) m <<= 1;
                for (int i = tid; i < m; i += NT) if ((uint32_t)i >= cnt) keys[i] = 0ull;
            }
        } else {
            m = 512; while (m < (int)cnt) m <<= 1;
            for (int i = tid; i < m; i += NT) if ((uint32_t)i >= cnt) keys[i] = 0ull;
        }
    } else {
        // ---- full fallback: exact 4096-bucket histogram select over whole batch ----
        const float4* lg4 = (const float4*)(logits + (size_t)b * NPER);
        for (int i = tid; i < 4096; i += NT) fbh[i] = 0;
        __syncthreads();
        for (int i = tid; i < N4; i += NT) {
            float4 v = lg4[i];
            atomicAdd(&fbh[fkey(v.x) >> 20], 1u);
            atomicAdd(&fbh[fkey(v.y) >> 20], 1u);
            atomicAdd(&fbh[fkey(v.z) >> 20], 1u);
            atomicAdd(&fbh[fkey(v.w) >> 20], 1u);
        }
        __syncthreads();
        uint32_t csum = 0;
        #pragma unroll
        for (int c = 0; c < 8; ++c) csum += fbh[tid * 8 + c];
        S[tid] = csum; __syncthreads();
        for (int off = 1; off < NT; off <<= 1) {
            uint32_t v2 = S[tid] + ((tid + off < NT) ? S[tid + off] : 0u);
            __syncthreads(); S[tid] = v2; __syncthreads();
        }
        {
            uint32_t after = (tid == NT - 1) ? 0u : S[tid + 1];
            uint32_t mine  = S[tid];
            if (after < TOPK && mine >= TOPK) {
                uint32_t run = after;
                for (int bk = tid * 8 + 7; bk >= tid * 8; --bk) {
                    run += fbh[bk];
                    if (run >= TOPK) { scal[0] = (uint32_t)bk; break; }
                }
            }
        }
        __syncthreads();
        uint32_t tb = scal[0];
        if (tb > 0) tb -= 1;                 // one-bucket margin for sigmoid ties
        const uint32_t thr = tb << 20;
        __syncthreads();
        for (int i = tid; i < N4; i += NT) {
            float4 v = lg4[i];
            float vv[4] = {v.x, v.y, v.z, v.w};
            #pragma unroll
            for (int c = 0; c < 4; ++c) {
                if (fkey(vv[c]) >= thr) {
                    uint32_t p = atomicAdd(&scal[1], 1u);
                    if (p < 2048u) keys[p] = make_key(vv[c], (uint32_t)(i * 4 + c));
                }
            }
        }
        __syncthreads();
        uint32_t c2 = scal[1]; if (c2 > 2048u) c2 = 2048u;
        m = 512; while (m < (int)c2) m <<= 1;
        for (int i = tid; i < m; i += NT) if ((uint32_t)i >= c2) keys[i] = 0ull;
    }
    __syncthreads();

    // ================= sort (descending) =================
    if (mode == 0) {
        // hybrid bitonic-512, 1 element/thread
        unsigned long long v = A[tid];
        #pragma unroll
        for (int k = 2; k <= 32; k <<= 1) {
            #pragma unroll
            for (int j = k >> 1; j; j >>= 1) {
                unsigned long long o = __shfl_xor_sync(0xffffffffu, v, j);
                bool mx = ((tid & k) == 0) ^ ((tid & j) != 0);
                v = mx ? (v > o ? v : o) : (v < o ? v : o);
            }
        }
        A[tid] = v; __syncthreads();
        #pragma unroll
        for (int k = 64; k <= 512; k <<= 1) {
            #pragma unroll
            for (int j = k >> 1; j >= 32; j >>= 1) {
                int ixj = tid ^ j;
                if (ixj > tid) {
                    unsigned long long a = A[tid], c = A[ixj];
                    bool desc = ((tid & k) == 0);
                    if (desc ? (a < c) : (a > c)) { A[tid] = c; A[ixj] = a; }
                }
                __syncthreads();
            }
            v = A[tid];
            bool desck = ((tid & k) == 0);
            #pragma unroll
            for (int j = 16; j; j >>= 1) {
                unsigned long long o = __shfl_xor_sync(0xffffffffu, v, j);
                bool mx = desck ^ ((tid & j) != 0);
                v = mx ? (v > o ? v : o) : (v < o ? v : o);
            }
            A[tid] = v; __syncthreads();
        }
    } else {
        // generic bitonic over m (512..2048), slot-strided
        for (int k = 2; k <= m; k <<= 1) {
            for (int j = k >> 1; j > 0; j >>= 1) {
                for (int i = tid; i < m; i += NT) {
                    int ixj = i ^ j;
                    if (ixj > i) {
                        unsigned long long a = A[i], c = A[ixj];
                        bool desc = ((i & k) == 0);
                        if (desc ? (a < c) : (a > c)) { A[i] = c; A[ixj] = a; }
                    }
                }
                __syncthreads();
            }
        }
    }

    // ================= emit top 300 =================
    if (tid < TOPK) {
        unsigned long long key = A[tid];
        uint32_t sbits = (uint32_t)(key >> 32);
        uint32_t idx   = 0xFFFFFFFFu - (uint32_t)(key & 0xFFFFFFFFull);
        if (idx >= NPER) idx = 0;          // OOB guard: never triggers on valid paths
        float score = __uint_as_float(sbits);
        int   label = (int)(idx % NCLS);
        int   q     = (int)(idx / NCLS);

        const float4 bx = ((const float4*)boxes)[b * 1000 + q];
        float cx = bx.x, cy = bx.y, w = bx.z, h = bx.w;

        int base = b * TOPK + tid;
        out[base] = (float)label;
        float* bo = out + BATCH * TOPK + (size_t)base * 4;
        bo[0] = cx - 0.5f * w;
        bo[1] = cy - 0.5f * h;
        bo[2] = cx + 0.5f * w;
        bo[3] = cy + 0.5f * h;
        out[BATCH * TOPK * 5 + base] = score;
    }
}

extern "C" void kernel_launch(void* const* d_in, const int* in_sizes, int n_in,
                              void* d_out, int out_size)
{
    const float* logits = (const float*)d_in[0];
    const float* boxes  = (const float*)d_in[1];
    float* out = (float*)d_out;

    const int smem = 16384 + 4096 + 4096 + 2048 + 64;   // 26,688 B < 48KB default
    postproc_fused<<<BATCH * 2, NT, smem>>>(logits, boxes, out);
}